// round 7
// baseline (speedup 1.0000x reference)
#include <cuda_runtime.h>
#include <math.h>

#define EPSf 1e-6f
#define NT 512

// ---- shared memory layout (float offsets), stride-102 rows, i is LOCAL (50 rows) ----
#define S1O   0        // s1R[ii*102+d]  (5100)
#define S2O   5100     // s2R[j*102+d]   (10200)
#define CMO   15300    // cm[ii*102+j]   (5100)
#define ATO   20400    // att[ii*102+d]  (5100)
#define WFO   25500    // w_full^2  [p*100+d] (1000)
#define WMO   26500    // w_maxpool^2
#define WEO   27500    // w_mean^2
#define WSO   28500    // w_slot4^2 (w7 fwd / w8 bwd)
#define R1WO  29500    // 1/n1w maxpool [ii*10+p] (500)
#define R2WO  30000    // 1/n2w maxpool [j*10+p] (1000)
#define R1O   31000    // 1/||s1_ii|| (50)
#define R2O   31050    // 1/||s2_j||  (100)
#define RSO   31150    // rowsum of cm per ii (50)
#define JMO   31200    // argmax j per ii (int) (50)
#define R2FO  31250    // 1/||s2_last * w_full_p|| per p (16)
#define MPO   31266    // maxpool scratch, 2 groups [grp*1250 + ii*25 + tx] (2500)
#define SMEM_FLOATS 33766

__device__ __forceinline__ float invs(float x) {
    return 1.0f / sqrtf(fmaxf(x, EPSf));
}

// packed fp32x2 FMA / MUL (sm_100+)
__device__ __forceinline__ float2 ffma2(float2 a, float2 b, float2 c) {
    unsigned long long ua = *reinterpret_cast<unsigned long long*>(&a);
    unsigned long long ub = *reinterpret_cast<unsigned long long*>(&b);
    unsigned long long uc = *reinterpret_cast<unsigned long long*>(&c);
    unsigned long long ud;
    asm("fma.rn.f32x2 %0, %1, %2, %3;" : "=l"(ud) : "l"(ua), "l"(ub), "l"(uc));
    return *reinterpret_cast<float2*>(&ud);
}
__device__ __forceinline__ float2 fmul2(float2 a, float2 b) {
    unsigned long long ua = *reinterpret_cast<unsigned long long*>(&a);
    unsigned long long ub = *reinterpret_cast<unsigned long long*>(&b);
    unsigned long long ud;
    asm("mul.rn.f32x2 %0, %1, %2;" : "=l"(ud) : "l"(ua), "l"(ub));
    return *reinterpret_cast<float2*>(&ud);
}

__global__ __launch_bounds__(NT, 1) void matching_kernel(
    const float* __restrict__ s1g, const float* __restrict__ s2g,
    const float* __restrict__ w1, const float* __restrict__ w2,
    const float* __restrict__ w3, const float* __restrict__ w4,
    const float* __restrict__ w5, const float* __restrict__ w6,
    const float* __restrict__ w7, const float* __restrict__ w8,
    float* __restrict__ out)
{
    extern __shared__ float sm[];
    const int b   = blockIdx.x;       // batch 0..255
    const int dir = blockIdx.y;       // 0=fwd, 1=bwd
    const int ib  = blockIdx.z * 50;  // i half: rows [ib, ib+50)
    const int tid = threadIdx.x;
    const int dOff = dir * 100;

    float* s1R  = sm + S1O;
    float* s2R  = sm + S2O;
    float* cm   = sm + CMO;
    float* att  = sm + ATO;

    // ================= phase 0: load weights (squared) + slices =============
    {
        const float* wf = dir ? w2 : w1;
        const float* wm = dir ? w4 : w3;
        const float* we = dir ? w6 : w5;
        const float* ws = dir ? w8 : w7;
        for (int e = tid; e < 1000; e += NT) {
            float a;
            a = wf[e]; sm[WFO + e] = a * a;
            a = wm[e]; sm[WMO + e] = a * a;
            a = we[e]; sm[WEO + e] = a * a;
            a = ws[e]; sm[WSO + e] = a * a;
        }
        for (int e = tid; e < 5000; e += NT) {       // s1 rows [ib, ib+50)
            int ii = e / 100, d = e - ii * 100;
            s1R[ii * 102 + d] = s1g[((size_t)(ib + ii) * 256 + b) * 200 + dOff + d];
        }
        for (int e = tid; e < 10000; e += NT) {      // s2 all 100 rows
            int j = e / 100, d = e - j * 100;
            s2R[j * 102 + d] = s2g[((size_t)j * 256 + b) * 200 + dOff + d];
        }
    }
    __syncthreads();

    // ================= phase 1: norms (parallel sub-jobs) ===================
    if (tid < 50) {                          // 1/||s1_ii||
        float2 a = make_float2(0.f, 0.f);
        for (int d = 0; d < 100; d += 2) {
            float2 v = *(const float2*)&s1R[tid * 102 + d];
            a = ffma2(v, v, a);
        }
        sm[R1O + tid] = invs(a.x + a.y);
    } else if (tid >= 64 && tid < 164) {     // 1/||s2_j||
        int j = tid - 64;
        float2 a = make_float2(0.f, 0.f);
        for (int d = 0; d < 100; d += 2) {
            float2 v = *(const float2*)&s2R[j * 102 + d];
            a = ffma2(v, v, a);
        }
        sm[R2O + j] = invs(a.x + a.y);
    } else if (tid >= 192 && tid < 202) {    // full's n2 on s2[99], per p
        const float* wp = sm + WFO + (tid - 192) * 100;
        float acc = 0.f;
        for (int d = 0; d < 100; d++) {
            float v = s2R[99 * 102 + d];
            acc = fmaf(v * v, wp[d], acc);
        }
        sm[R2FO + (tid - 192)] = invs(acc);
    } else if (tid >= 256 && tid < 316) {    // weighted norms as 5x5 tiles
        int t = tid - 256;                   // 0..59  (0..19 s1-local, 20..59 s2)
        int which = (t >= 20);
        int r = which ? (t - 20) : t;
        int i0 = (r / 2) * 5;
        int p0 = (r % 2) * 5;
        const float* base = which ? s2R : s1R;
        float2 acc[5][5];
        #pragma unroll
        for (int m = 0; m < 5; m++)
            #pragma unroll
            for (int q = 0; q < 5; q++) acc[m][q] = make_float2(0.f, 0.f);
        for (int d = 0; d < 100; d += 2) {
            float2 sq[5], wv[5];
            #pragma unroll
            for (int m = 0; m < 5; m++) {
                float2 v = *(const float2*)&base[(i0 + m) * 102 + d];
                sq[m] = fmul2(v, v);
            }
            #pragma unroll
            for (int q = 0; q < 5; q++)
                wv[q] = *(const float2*)&sm[WMO + (p0 + q) * 100 + d];
            #pragma unroll
            for (int m = 0; m < 5; m++)
                #pragma unroll
                for (int q = 0; q < 5; q++) acc[m][q] = ffma2(sq[m], wv[q], acc[m][q]);
        }
        float* dst = sm + (which ? R2WO : R1WO);
        #pragma unroll
        for (int m = 0; m < 5; m++)
            #pragma unroll
            for (int q = 0; q < 5; q++)
                dst[(i0 + m) * 10 + p0 + q] = invs(acc[m][q].x + acc[m][q].y);
    }
    __syncthreads();

    // ================= phase 2: cosm GEMM (250 thr, 5x4 tile, f32x2/d) =====
    if (tid < 250) {
        const int ty = tid / 25;       // 0..9
        const int tx = tid - ty * 25;  // 0..24
        const int i0 = ty * 5;
        float2 acc[5][4];
        #pragma unroll
        for (int m = 0; m < 5; m++)
            #pragma unroll
            for (int n = 0; n < 4; n++) acc[m][n] = make_float2(0.f, 0.f);
        for (int d = 0; d < 100; d += 2) {
            float2 bv[4];
            #pragma unroll
            for (int n = 0; n < 4; n++)
                bv[n] = *(const float2*)&s2R[(tx + 25 * n) * 102 + d];
            #pragma unroll
            for (int m = 0; m < 5; m++) {
                float2 a = *(const float2*)&s1R[(i0 + m) * 102 + d];
                #pragma unroll
                for (int n = 0; n < 4; n++) acc[m][n] = ffma2(a, bv[n], acc[m][n]);
            }
        }
        #pragma unroll
        for (int m = 0; m < 5; m++) {
            int ii = i0 + m;
            float r1 = sm[R1O + ii];
            #pragma unroll
            for (int n = 0; n < 4; n++) {
                int j = tx + 25 * n;
                cm[ii * 102 + j] = (acc[m][n].x + acc[m][n].y) * r1 * sm[R2O + j];
            }
        }
    }
    __syncthreads();

    // ================= phase 3: rowsum + argmax (first-max) =================
    if (tid < 50) {
        float rs = 0.f, best = -1e30f; int bj = 0;
        for (int j = 0; j < 100; j++) {
            float v = cm[tid * 102 + j];
            rs += v;
            if (v > best) { best = v; bj = j; }
        }
        sm[RSO + tid] = rs;
        reinterpret_cast<int*>(sm)[JMO + tid] = bj;
    }
    __syncthreads();

    // ====== phase 4: maxpool — 2 groups x 5 p, 5x4 tile over 50i x 100j ====
    {
        const int grp = tid / 250;         // 0 or 1 (tid>=500 idle)
        const int t   = tid - grp * 250;   // 0..249
        const int ty  = t / 25;            // 0..9
        const int tx  = t - ty * 25;       // 0..24
        const int i0  = ty * 5;
        for (int pi = 0; pi < 5; pi++) {
            if (tid < 500) {
                const int p = grp * 5 + pi;
                float2 acc[5][4];
                #pragma unroll
                for (int m = 0; m < 5; m++)
                    #pragma unroll
                    for (int n = 0; n < 4; n++) acc[m][n] = make_float2(0.f, 0.f);
                const float* wp = sm + WMO + p * 100;
                for (int d = 0; d < 100; d += 2) {
                    float2 wv = *(const float2*)&wp[d];
                    float2 bv[4];
                    #pragma unroll
                    for (int n = 0; n < 4; n++)
                        bv[n] = fmul2(*(const float2*)&s2R[(tx + 25 * n) * 102 + d], wv);
                    #pragma unroll
                    for (int m = 0; m < 5; m++) {
                        float2 a = *(const float2*)&s1R[(i0 + m) * 102 + d];
                        #pragma unroll
                        for (int n = 0; n < 4; n++) acc[m][n] = ffma2(a, bv[n], acc[m][n]);
                    }
                }
                #pragma unroll
                for (int m = 0; m < 5; m++) {
                    int ii = i0 + m;
                    float r1 = sm[R1WO + ii * 10 + p];
                    float pm = -1e30f;
                    #pragma unroll
                    for (int n = 0; n < 4; n++) {
                        int j = tx + 25 * n;
                        pm = fmaxf(pm, (acc[m][n].x + acc[m][n].y) * r1 * sm[R2WO + j * 10 + p]);
                    }
                    sm[MPO + grp * 1250 + ii * 25 + tx] = pm;
                }
            }
            __syncthreads();
            if (tid < 100) {
                int g = tid / 50, ii = tid - g * 50;
                float mv = -1e30f;
                #pragma unroll 5
                for (int k = 0; k < 25; k++)
                    mv = fmaxf(mv, sm[MPO + g * 1250 + ii * 25 + k]);
                out[((size_t)(ib + ii) * 256 + b) * 80 + 20 + dir * 10 + (g * 5 + pi)] = mv;
            }
            __syncthreads();
        }
    }

    // ====== phase 5: mean attention GEMM (250 thr, 5x4 tile, f32x2/j) ======
    if (tid < 250) {
        const int ty = tid / 25;
        const int tx = tid - ty * 25;
        const int i0 = ty * 5;
        float2 acc[5][4];
        #pragma unroll
        for (int m = 0; m < 5; m++)
            #pragma unroll
            for (int n = 0; n < 4; n++) acc[m][n] = make_float2(0.f, 0.f);
        for (int j = 0; j < 100; j += 2) {
            float2 bv[4];
            #pragma unroll
            for (int n = 0; n < 4; n++) {
                int dc = tx + 25 * n;
                bv[n] = make_float2(s2R[j * 102 + dc], s2R[(j + 1) * 102 + dc]);
            }
            #pragma unroll
            for (int m = 0; m < 5; m++) {
                float2 a = *(const float2*)&cm[(i0 + m) * 102 + j];
                #pragma unroll
                for (int n = 0; n < 4; n++) acc[m][n] = ffma2(a, bv[n], acc[m][n]);
            }
        }
        #pragma unroll
        for (int m = 0; m < 5; m++) {
            int ii = i0 + m;
            float rd = 1.0f / (sm[RSO + ii] + EPSf);
            #pragma unroll
            for (int n = 0; n < 4; n++) {
                int d = tx + 25 * n;
                att[ii * 102 + d] = (acc[m][n].x + acc[m][n].y) * rd;
            }
        }
    }
    __syncthreads();

    // ======== phase 6: features — full, mean-att, and (dir==1) slot4 =======
    if (tid < 500) {
        int ii = tid / 10, p = tid - ii * 10;
        const float* wfp = sm + WFO + p * 100;
        const float* wep = sm + WEO + p * 100;
        const float* wsp = sm + WSO + p * 100;
        float numF = 0.f, n1F = 0.f;
        float numE = 0.f, n1E = 0.f, n2E = 0.f;
        float numS = 0.f, n1S = 0.f, n2S = 0.f;
        for (int d = 0; d < 100; d++) {
            float v1 = s1R[ii * 102 + d];
            float v2l = s2R[99 * 102 + d];
            float av = att[ii * 102 + d];
            float wf2 = wfp[d], we2 = wep[d];
            numF = fmaf(v1 * v2l, wf2, numF);
            n1F  = fmaf(v1 * v1,  wf2, n1F);
            numE = fmaf(v1 * av,  we2, numE);
            n1E  = fmaf(v1 * v1,  we2, n1E);
            n2E  = fmaf(av * av,  we2, n2E);
            if (dir == 1) {
                float ws2 = wsp[d];
                numS = fmaf(v1 * av, ws2, numS);
                n1S  = fmaf(v1 * v1, ws2, n1S);
                n2S  = fmaf(av * av, ws2, n2S);
            }
        }
        size_t ob = ((size_t)(ib + ii) * 256 + b) * 80 + dir * 10 + p;
        out[ob +  0] = numF * invs(n1F) * sm[R2FO + p];
        out[ob + 40] = numE * invs(n1E) * invs(n2E);
        if (dir == 1)
            out[ob + 60] = numS * invs(n1S) * invs(n2S);
    }
    __syncthreads();

    // ======== phase 7 (dir==0 only): max-att gather + w7 features ==========
    // Reference bug reproduced: att vector = s2[seq=0, batch=jmax, fwd slice]
    if (dir == 0) {
        for (int e = tid; e < 5000; e += NT) {
            int ii = e / 100, d = e - ii * 100;
            int jm = reinterpret_cast<int*>(sm)[JMO + ii];
            att[ii * 102 + d] = __ldg(&s2g[(size_t)jm * 200 + d]);
        }
        __syncthreads();
        if (tid < 500) {
            int ii = tid / 10, p = tid - ii * 10;
            const float* wsp = sm + WSO + p * 100;
            float num = 0.f, n1 = 0.f, n2 = 0.f;
            for (int d = 0; d < 100; d++) {
                float v1 = s1R[ii * 102 + d];
                float av = att[ii * 102 + d];
                float ws2 = wsp[d];
                num = fmaf(v1 * av, ws2, num);
                n1  = fmaf(v1 * v1, ws2, n1);
                n2  = fmaf(av * av, ws2, n2);
            }
            out[((size_t)(ib + ii) * 256 + b) * 80 + 60 + p] = num * invs(n1) * invs(n2);
        }
    }
}

extern "C" void kernel_launch(void* const* d_in, const int* in_sizes, int n_in,
                              void* d_out, int out_size) {
    const float* s1 = (const float*)d_in[0];
    const float* s2 = (const float*)d_in[1];
    const float* w1 = (const float*)d_in[2];
    const float* w2 = (const float*)d_in[3];
    const float* w3 = (const float*)d_in[4];
    const float* w4 = (const float*)d_in[5];
    const float* w5 = (const float*)d_in[6];
    const float* w6 = (const float*)d_in[7];
    const float* w7 = (const float*)d_in[8];
    const float* w8 = (const float*)d_in[9];
    float* out = (float*)d_out;

    static bool attr_set = false;
    if (!attr_set) {
        cudaFuncSetAttribute(matching_kernel,
                             cudaFuncAttributeMaxDynamicSharedMemorySize,
                             SMEM_FLOATS * (int)sizeof(float));
        attr_set = true;
    }
    dim3 grid(256, 2, 2);
    matching_kernel<<<grid, NT, SMEM_FLOATS * sizeof(float)>>>(
        s1, s2, w1, w2, w3, w4, w5, w6, w7, w8, out);
}

// round 8
// speedup vs baseline: 1.2965x; 1.2965x over previous
#include <cuda_runtime.h>
#include <math.h>

#define EPSf 1e-6f
#define NT 512
#define STR 108   // row stride in floats: float4-aligned, 27*tx mod 8 is a permutation

// ---- shared memory layout (float offsets), stride-108 rows ----
#define S1O   0        // s1R[i*108+d]   (10800)
#define S2O   10800    // s2R[j*108+d]   (10800)
#define CMO   21600    // cosm[i*108+j]  (10800)
#define ATO   32400    // att[i*108+d]   (10800)
#define WFO   43200    // w_full^2  [p*100+d] (1000)
#define WMO   44200    // w_maxpool^2
#define WEO   45200    // w_mean^2
#define WSO   46200    // w_slot4^2 (w7 fwd / w8 bwd)
#define R1WO  47200    // 1/n1w maxpool [i*10+p] (1000)
#define R2WO  48200    // 1/n2w maxpool [j*10+p] (1000)
#define R1O   49200    // 1/||s1_i||  (100)
#define R2O   49300    // 1/||s2_j||  (100)
#define RSO   49400    // rowsum of cosm per i (100)
#define JMO   49500    // argmax j per i (int) (100)
#define R2FO  49600    // 1/||s2_last * w_full_p|| per p (16)
#define MPO   49616    // maxpool scratch, 2 groups [grp*2500 + i*25 + tx] (5000)
#define SMEM_FLOATS 54616

__device__ __forceinline__ float invs(float x) {
    return 1.0f / sqrtf(fmaxf(x, EPSf));
}

// packed fp32x2 FMA / MUL (sm_100+)
__device__ __forceinline__ float2 ffma2(float2 a, float2 b, float2 c) {
    unsigned long long ua = *reinterpret_cast<unsigned long long*>(&a);
    unsigned long long ub = *reinterpret_cast<unsigned long long*>(&b);
    unsigned long long uc = *reinterpret_cast<unsigned long long*>(&c);
    unsigned long long ud;
    asm("fma.rn.f32x2 %0, %1, %2, %3;" : "=l"(ud) : "l"(ua), "l"(ub), "l"(uc));
    return *reinterpret_cast<float2*>(&ud);
}
__device__ __forceinline__ float2 fmul2(float2 a, float2 b) {
    unsigned long long ua = *reinterpret_cast<unsigned long long*>(&a);
    unsigned long long ub = *reinterpret_cast<unsigned long long*>(&b);
    unsigned long long ud;
    asm("mul.rn.f32x2 %0, %1, %2;" : "=l"(ud) : "l"(ua), "l"(ub));
    return *reinterpret_cast<float2*>(&ud);
}

__global__ __launch_bounds__(NT, 1) void matching_kernel(
    const float* __restrict__ s1g, const float* __restrict__ s2g,
    const float* __restrict__ w1, const float* __restrict__ w2,
    const float* __restrict__ w3, const float* __restrict__ w4,
    const float* __restrict__ w5, const float* __restrict__ w6,
    const float* __restrict__ w7, const float* __restrict__ w8,
    float* __restrict__ out)
{
    extern __shared__ float sm[];
    const int b   = blockIdx.x;   // batch 0..255
    const int dir = blockIdx.y;   // 0=fwd, 1=bwd
    const int tid = threadIdx.x;
    const int dOff = dir * 100;

    float* s1R  = sm + S1O;
    float* s2R  = sm + S2O;
    float* cm   = sm + CMO;
    float* att  = sm + ATO;

    // ================= phase 0: load weights (squared) + s1/s2 slices ======
    {
        const float* wf = dir ? w2 : w1;
        const float* wm = dir ? w4 : w3;
        const float* we = dir ? w6 : w5;
        const float* ws = dir ? w8 : w7;
        for (int e = tid; e < 1000; e += NT) {
            float a;
            a = wf[e]; sm[WFO + e] = a * a;
            a = wm[e]; sm[WMO + e] = a * a;
            a = we[e]; sm[WEO + e] = a * a;
            a = ws[e]; sm[WSO + e] = a * a;
        }
        for (int e = tid; e < 10000; e += NT) {
            int i = e / 100, d = e - i * 100;
            size_t g = ((size_t)i * 256 + b) * 200 + dOff + d;
            s1R[i * STR + d] = s1g[g];
            s2R[i * STR + d] = s2g[g];
        }
    }
    __syncthreads();

    // ================= phase 1: norms (parallel sub-jobs) ==================
    if (tid < 200) {                        // unweighted 1/||.|| for cosm
        int idx = tid % 100;
        const float* base = (tid < 100) ? s1R : s2R;
        float2 s2a = make_float2(0.f, 0.f);
        for (int d = 0; d < 100; d += 2) {
            float2 v = *(const float2*)&base[idx * STR + d];
            s2a = ffma2(v, v, s2a);
        }
        sm[(tid < 100 ? R1O : R2O) + idx] = invs(s2a.x + s2a.y);
    } else if (tid >= 240 && tid < 250) {   // full's n2: s2[99] weighted norms per p
        const float* wp = sm + WFO + (tid - 240) * 100;
        float acc = 0.f;
        for (int d = 0; d < 100; d++) {
            float v = s2R[99 * STR + d];
            acc = fmaf(v * v, wp[d], acc);
        }
        sm[R2FO + (tid - 240)] = invs(acc);
    } else if (tid >= 256 && tid < 336) {   // maxpool weighted norms as 5x5 GEMM tiles
        int t = tid - 256;                  // 0..79
        int which = t / 40;                 // 0: s1, 1: s2
        int r = t - which * 40;             // 0..39
        int i0 = (r / 2) * 5;               // 0,5,...,95
        int p0 = (r % 2) * 5;               // 0 or 5
        const float* base = which ? s2R : s1R;
        float2 acc[5][5];
        #pragma unroll
        for (int m = 0; m < 5; m++)
            #pragma unroll
            for (int q = 0; q < 5; q++) acc[m][q] = make_float2(0.f, 0.f);
        for (int d = 0; d < 100; d += 2) {
            float2 sq[5], wv[5];
            #pragma unroll
            for (int m = 0; m < 5; m++) {
                float2 v = *(const float2*)&base[(i0 + m) * STR + d];
                sq[m] = fmul2(v, v);
            }
            #pragma unroll
            for (int q = 0; q < 5; q++)
                wv[q] = *(const float2*)&sm[WMO + (p0 + q) * 100 + d];
            #pragma unroll
            for (int m = 0; m < 5; m++)
                #pragma unroll
                for (int q = 0; q < 5; q++) acc[m][q] = ffma2(sq[m], wv[q], acc[m][q]);
        }
        float* dst = sm + (which ? R2WO : R1WO);
        #pragma unroll
        for (int m = 0; m < 5; m++)
            #pragma unroll
            for (int q = 0; q < 5; q++)
                dst[(i0 + m) * 10 + p0 + q] = invs(acc[m][q].x + acc[m][q].y);
    }
    __syncthreads();

    // ============ phase 2: cosm GEMM (250 thr, 10x4 tile, float4/d) ========
    if (tid < 250) {
        const int ty = tid / 25;       // 0..9
        const int tx = tid - ty * 25;  // 0..24
        const int i0 = ty * 10;
        float2 acc[10][4];
        #pragma unroll
        for (int m = 0; m < 10; m++)
            #pragma unroll
            for (int n = 0; n < 4; n++) acc[m][n] = make_float2(0.f, 0.f);
        for (int d = 0; d < 100; d += 4) {
            float4 bv[4];
            #pragma unroll
            for (int n = 0; n < 4; n++)
                bv[n] = *(const float4*)&s2R[(tx + 25 * n) * STR + d];
            #pragma unroll
            for (int m = 0; m < 10; m++) {
                float4 a = *(const float4*)&s1R[(i0 + m) * STR + d];
                float2 alo = make_float2(a.x, a.y), ahi = make_float2(a.z, a.w);
                #pragma unroll
                for (int n = 0; n < 4; n++) {
                    acc[m][n] = ffma2(alo, make_float2(bv[n].x, bv[n].y), acc[m][n]);
                    acc[m][n] = ffma2(ahi, make_float2(bv[n].z, bv[n].w), acc[m][n]);
                }
            }
        }
        #pragma unroll
        for (int m = 0; m < 10; m++) {
            int i = i0 + m;
            float r1 = sm[R1O + i];
            #pragma unroll
            for (int n = 0; n < 4; n++) {
                int j = tx + 25 * n;
                cm[i * STR + j] = (acc[m][n].x + acc[m][n].y) * r1 * sm[R2O + j];
            }
        }
    }
    __syncthreads();

    // ================= phase 3: rowsum + argmax (first-max) ================
    if (tid < 100) {
        float rs = 0.f, best = -1e30f; int bj = 0;
        for (int j = 0; j < 100; j++) {
            float v = cm[tid * STR + j];
            rs += v;
            if (v > best) { best = v; bj = j; }
        }
        sm[RSO + tid] = rs;
        reinterpret_cast<int*>(sm)[JMO + tid] = bj;
    }
    __syncthreads();

    // ====== phase 4: maxpool — 2 grp x 5 p, 10x4 tile, float4 over d =======
    {
        const int grp = tid / 250;         // 0 or 1 (tid>=500 idle)
        const int t   = tid - grp * 250;   // 0..249
        const int ty  = t / 25;            // 0..9
        const int tx  = t - ty * 25;       // 0..24
        const int i0  = ty * 10;
        for (int pi = 0; pi < 5; pi++) {
            if (tid < 500) {
                const int p = grp * 5 + pi;
                float2 acc[10][4];
                #pragma unroll
                for (int m = 0; m < 10; m++)
                    #pragma unroll
                    for (int n = 0; n < 4; n++) acc[m][n] = make_float2(0.f, 0.f);
                const float* wp = sm + WMO + p * 100;
                for (int d = 0; d < 100; d += 4) {
                    float4 wv4 = *(const float4*)&wp[d];
                    float2 wlo = make_float2(wv4.x, wv4.y), whi = make_float2(wv4.z, wv4.w);
                    float2 blo[4], bhi[4];
                    #pragma unroll
                    for (int n = 0; n < 4; n++) {
                        float4 bv = *(const float4*)&s2R[(tx + 25 * n) * STR + d];
                        blo[n] = fmul2(make_float2(bv.x, bv.y), wlo);
                        bhi[n] = fmul2(make_float2(bv.z, bv.w), whi);
                    }
                    #pragma unroll
                    for (int m = 0; m < 10; m++) {
                        float4 a = *(const float4*)&s1R[(i0 + m) * STR + d];
                        float2 alo = make_float2(a.x, a.y), ahi = make_float2(a.z, a.w);
                        #pragma unroll
                        for (int n = 0; n < 4; n++) {
                            acc[m][n] = ffma2(alo, blo[n], acc[m][n]);
                            acc[m][n] = ffma2(ahi, bhi[n], acc[m][n]);
                        }
                    }
                }
                #pragma unroll
                for (int m = 0; m < 10; m++) {
                    int i = i0 + m;
                    float r1 = sm[R1WO + i * 10 + p];
                    float pm = -1e30f;
                    #pragma unroll
                    for (int n = 0; n < 4; n++) {
                        int j = tx + 25 * n;
                        pm = fmaxf(pm, (acc[m][n].x + acc[m][n].y) * r1 * sm[R2WO + j * 10 + p]);
                    }
                    sm[MPO + grp * 2500 + i * 25 + tx] = pm;
                }
            }
            __syncthreads();
            if (tid < 200) {
                int g = tid / 100, i = tid - g * 100;
                float mv = -1e30f;
                #pragma unroll 5
                for (int k = 0; k < 25; k++)
                    mv = fmaxf(mv, sm[MPO + g * 2500 + i * 25 + k]);
                out[((size_t)i * 256 + b) * 80 + 20 + dir * 10 + (g * 5 + pi)] = mv;
            }
            __syncthreads();
        }
    }

    // ====== phase 5: mean attention GEMM (250 thr, 10x4, f32x2/j) ==========
    if (tid < 250) {
        const int ty = tid / 25;
        const int tx = tid - ty * 25;
        const int i0 = ty * 10;
        float2 acc[10][4];
        #pragma unroll
        for (int m = 0; m < 10; m++)
            #pragma unroll
            for (int n = 0; n < 4; n++) acc[m][n] = make_float2(0.f, 0.f);
        for (int j = 0; j < 100; j += 2) {
            float2 bv[4];
            #pragma unroll
            for (int n = 0; n < 4; n++) {
                int dc = tx + 25 * n;
                bv[n] = make_float2(s2R[j * STR + dc], s2R[(j + 1) * STR + dc]);
            }
            #pragma unroll
            for (int m = 0; m < 10; m++) {
                float2 a = *(const float2*)&cm[(i0 + m) * STR + j];
                #pragma unroll
                for (int n = 0; n < 4; n++) acc[m][n] = ffma2(a, bv[n], acc[m][n]);
            }
        }
        #pragma unroll
        for (int m = 0; m < 10; m++) {
            int i = i0 + m;
            float rd = 1.0f / (sm[RSO + i] + EPSf);
            #pragma unroll
            for (int n = 0; n < 4; n++) {
                int d = tx + 25 * n;
                att[i * STR + d] = (acc[m][n].x + acc[m][n].y) * rd;
            }
        }
    }
    __syncthreads();

    // ======== phase 6: features — full, mean-att, and (dir==1) slot4 =======
    for (int r = 0; r < 2; r++) {
        int task = tid + NT * r;
        if (task < 1000) {
            int i = task / 10, p = task - i * 10;
            const float* wfp = sm + WFO + p * 100;
            const float* wep = sm + WEO + p * 100;
            const float* wsp = sm + WSO + p * 100;
            float numF = 0.f, n1F = 0.f;
            float numE = 0.f, n1E = 0.f, n2E = 0.f;
            float numS = 0.f, n1S = 0.f, n2S = 0.f;
            for (int d = 0; d < 100; d++) {
                float v1 = s1R[i * STR + d];
                float v2l = s2R[99 * STR + d];
                float av = att[i * STR + d];
                float wf2 = wfp[d], we2 = wep[d];
                numF = fmaf(v1 * v2l, wf2, numF);
                n1F  = fmaf(v1 * v1,  wf2, n1F);
                numE = fmaf(v1 * av,  we2, numE);
                n1E  = fmaf(v1 * v1,  we2, n1E);
                n2E  = fmaf(av * av,  we2, n2E);
                if (dir == 1) {
                    float ws2 = wsp[d];
                    numS = fmaf(v1 * av, ws2, numS);
                    n1S  = fmaf(v1 * v1, ws2, n1S);
                    n2S  = fmaf(av * av, ws2, n2S);
                }
            }
            size_t ob = ((size_t)i * 256 + b) * 80 + dir * 10 + p;
            out[ob +  0] = numF * invs(n1F) * sm[R2FO + p];
            out[ob + 40] = numE * invs(n1E) * invs(n2E);
            if (dir == 1)
                out[ob + 60] = numS * invs(n1S) * invs(n2S);
        }
    }
    __syncthreads();

    // ======== phase 7 (dir==0 only): max-att gather + w7 features ==========
    // Reference bug reproduced: att vector = s2[seq=0, batch=jmax, fwd slice]
    if (dir == 0) {
        for (int e = tid; e < 10000; e += NT) {
            int i = e / 100, d = e - i * 100;
            int jm = reinterpret_cast<int*>(sm)[JMO + i];
            att[i * STR + d] = __ldg(&s2g[(size_t)jm * 200 + d]);
        }
        __syncthreads();
        for (int r = 0; r < 2; r++) {
            int task = tid + NT * r;
            if (task < 1000) {
                int i = task / 10, p = task - i * 10;
                const float* wsp = sm + WSO + p * 100;
                float num = 0.f, n1 = 0.f, n2 = 0.f;
                for (int d = 0; d < 100; d++) {
                    float v1 = s1R[i * STR + d];
                    float av = att[i * STR + d];
                    float ws2 = wsp[d];
                    num = fmaf(v1 * av, ws2, num);
                    n1  = fmaf(v1 * v1, ws2, n1);
                    n2  = fmaf(av * av, ws2, n2);
                }
                out[((size_t)i * 256 + b) * 80 + 60 + p] = num * invs(n1) * invs(n2);
            }
        }
    }
}

extern "C" void kernel_launch(void* const* d_in, const int* in_sizes, int n_in,
                              void* d_out, int out_size) {
    const float* s1 = (const float*)d_in[0];
    const float* s2 = (const float*)d_in[1];
    const float* w1 = (const float*)d_in[2];
    const float* w2 = (const float*)d_in[3];
    const float* w3 = (const float*)d_in[4];
    const float* w4 = (const float*)d_in[5];
    const float* w5 = (const float*)d_in[6];
    const float* w6 = (const float*)d_in[7];
    const float* w7 = (const float*)d_in[8];
    const float* w8 = (const float*)d_in[9];
    float* out = (float*)d_out;

    static bool attr_set = false;
    if (!attr_set) {
        cudaFuncSetAttribute(matching_kernel,
                             cudaFuncAttributeMaxDynamicSharedMemorySize,
                             SMEM_FLOATS * (int)sizeof(float));
        attr_set = true;
    }
    dim3 grid(256, 2);
    matching_kernel<<<grid, NT, SMEM_FLOATS * sizeof(float)>>>(
        s1, s2, w1, w2, w3, w4, w5, w6, w7, w8, out);
}